// round 9
// baseline (speedup 1.0000x reference)
#include <cuda_runtime.h>
#include <cuda_fp16.h>
#include <math.h>

// Problem constants (fixed by dataset)
#define MAXN 100000
#define MAXE 1600000
#define NEG_SLOPE 0.2f

// ---------------- scratch (static __device__, no allocs) ----------------
__device__ __half g_h[(size_t)MAXN * 128];    // 25.6 MB: h = elu(x)@W, [N,128] fp16
__device__ float g_asrc[MAXN * 2];            // per-node attention halves
__device__ float g_adst[MAXN * 2];
__device__ int   g_deg[MAXN];
__device__ int   g_starts[MAXN + 1];
__device__ int   g_cursor[MAXN];
__device__ int   g_ssrc[MAXE + MAXN];         // src index sorted by dst (incl self loops)

// ---------------- helpers ----------------
__device__ __forceinline__ float elu_f(float v)   { return v > 0.f ? v : expm1f(v); }
__device__ __forceinline__ float lrelu_f(float v) { return v > 0.f ? v : NEG_SLOPE * v; }

// ---------------- K0: init degrees (1 = self loop) + cursors ----------------
__global__ void k_init(int n) {
    int i = blockIdx.x * blockDim.x + threadIdx.x;
    if (i < n) { g_deg[i] = 1; g_cursor[i] = 0; }
}

// ---------------- K1: histogram of dst (edge_index is int32) ----------------
__global__ void k_hist(const int* __restrict__ ei, int e) {
    int i = blockIdx.x * blockDim.x + threadIdx.x;
    if (i < e) {
        int d = ei[e + i];
        atomicAdd(&g_deg[d], 1);
    }
}

// ---------------- K2: single-block exclusive scan over deg -> starts ----------------
__global__ void k_scan(int n) {
    __shared__ int part[1024];
    int tid = threadIdx.x;
    int chunk = (n + 1023) >> 10;
    int base = tid * chunk;
    int s = 0;
    for (int i = 0; i < chunk; i++) {
        int id = base + i;
        if (id < n) s += g_deg[id];
    }
    part[tid] = s;
    __syncthreads();
    for (int off = 1; off < 1024; off <<= 1) {
        int v = (tid >= off) ? part[tid - off] : 0;
        __syncthreads();
        part[tid] += v;
        __syncthreads();
    }
    int run = tid ? part[tid - 1] : 0;
    for (int i = 0; i < chunk; i++) {
        int id = base + i;
        if (id < n) { g_starts[id] = run; run += g_deg[id]; }
    }
    if (tid == 1023) g_starts[n] = part[1023];
}

// ---------------- K3: scatter edges into dst-sorted order; self loop at segment end ----------------
__global__ void k_scatter(const int* __restrict__ ei, int e, int n) {
    int i = blockIdx.x * blockDim.x + threadIdx.x;
    if (i < e) {
        int s = ei[i];
        int d = ei[e + i];
        int p = g_starts[d] + atomicAdd(&g_cursor[d], 1);
        g_ssrc[p] = s;
    } else if (i < e + n) {
        int nn = i - e;                     // self loop (nn -> nn)
        g_ssrc[g_starts[nn + 1] - 1] = nn;  // slot deg-1 is reserved for it
    }
}

// ---------------- K4: tensor-core h = elu(x) @ W + att epilogue ----------------
// Block: 256 threads (8 warps). Tile: 64 nodes x 128 outs, K=128 in two 64-halves.
// Warp w: mw=w&3 rows [mw*16,+16), nw=w>>2 cols [nw*64,+64). mma m16n8k16 fp16->fp32.
// smem: sX [64][72] fp16 (x, elu'd), sW [128][72] fp16 (W transposed: [n][k]).
// After mainloop, sD [64][136] fp16 aliases the operand buffers for the epilogue.
#define SX_STRIDE 72
#define SW_STRIDE 72
#define SD_STRIDE 136
#define SX_BYTES (64 * SX_STRIDE * 2)          // 9216
#define SW_BYTES (128 * SW_STRIDE * 2)         // 18432

__global__ __launch_bounds__(256) void k_gemm(const float* __restrict__ x,
                                              const float* __restrict__ W,
                                              const float* __restrict__ att_src,
                                              const float* __restrict__ att_dst, int n) {
    __shared__ __align__(16) char buf[SX_BYTES + SW_BYTES];
    __half* sX = (__half*)buf;                 // [64][SX_STRIDE]
    __half* sW = (__half*)(buf + SX_BYTES);    // [128][SW_STRIDE] = W^T [n][k]
    __half* sD = (__half*)buf;                 // [64][SD_STRIDE] alias, used post-loop

    int tid = threadIdx.x;
    int lane = tid & 31, w = tid >> 5;
    int mw = w & 3, nw = w >> 2;
    int g = lane >> 2, t = lane & 3;
    int nodeBase = blockIdx.x * 64;

    float acc[8][4];
    #pragma unroll
    for (int nf = 0; nf < 8; nf++)
        #pragma unroll
        for (int c = 0; c < 4; c++) acc[nf][c] = 0.f;

    for (int kk = 0; kk < 128; kk += 64) {
        // load x tile (64 nodes x 64 k), elu, fp16
        #pragma unroll
        for (int j = 0; j < 4; j++) {
            int slot = j * 256 + tid;          // 1024 float4 slots
            int row = slot >> 4, c4 = slot & 15;
            int gn = nodeBase + row;
            float4 v = make_float4(0.f, 0.f, 0.f, 0.f);
            if (gn < n) v = *(const float4*)(x + (size_t)gn * 128 + kk + c4 * 4);
            v.x = elu_f(v.x); v.y = elu_f(v.y); v.z = elu_f(v.z); v.w = elu_f(v.w);
            __half2 h01 = __floats2half2_rn(v.x, v.y);
            __half2 h23 = __floats2half2_rn(v.z, v.w);
            __half2* dst = (__half2*)(sX + row * SX_STRIDE + c4 * 4);
            dst[0] = h01; dst[1] = h23;
        }
        // load W rows kk..kk+63, transpose into sW[n][k]
        #pragma unroll
        for (int j = 0; j < 8; j++) {
            int slot = j * 256 + tid;          // 2048 float4 slots
            int k = slot >> 5, c4 = slot & 31;
            float4 v = *(const float4*)(W + (size_t)(kk + k) * 128 + c4 * 4);
            sW[(c4 * 4 + 0) * SW_STRIDE + k] = __float2half_rn(v.x);
            sW[(c4 * 4 + 1) * SW_STRIDE + k] = __float2half_rn(v.y);
            sW[(c4 * 4 + 2) * SW_STRIDE + k] = __float2half_rn(v.z);
            sW[(c4 * 4 + 3) * SW_STRIDE + k] = __float2half_rn(v.w);
        }
        __syncthreads();

        #pragma unroll
        for (int ks = 0; ks < 4; ks++) {
            int kb = ks * 16;
            const __half* ax = sX + (mw * 16 + g) * SX_STRIDE + kb;
            unsigned a0 = *(const unsigned*)(ax + 2 * t);
            unsigned a1 = *(const unsigned*)(ax + 8 * SX_STRIDE + 2 * t);
            unsigned a2 = *(const unsigned*)(ax + 8 + 2 * t);
            unsigned a3 = *(const unsigned*)(ax + 8 * SX_STRIDE + 8 + 2 * t);
            #pragma unroll
            for (int nf = 0; nf < 8; nf++) {
                const __half* bx = sW + (nw * 64 + nf * 8 + g) * SW_STRIDE + kb;
                unsigned b0 = *(const unsigned*)(bx + 2 * t);
                unsigned b1 = *(const unsigned*)(bx + 8 + 2 * t);
                asm volatile(
                    "mma.sync.aligned.m16n8k16.row.col.f32.f16.f16.f32 "
                    "{%0,%1,%2,%3}, {%4,%5,%6,%7}, {%8,%9}, {%0,%1,%2,%3};"
                    : "+f"(acc[nf][0]), "+f"(acc[nf][1]), "+f"(acc[nf][2]), "+f"(acc[nf][3])
                    : "r"(a0), "r"(a1), "r"(a2), "r"(a3), "r"(b0), "r"(b1));
            }
        }
        __syncthreads();
    }

    // stage D -> sD (fp16)
    #pragma unroll
    for (int nf = 0; nf < 8; nf++) {
        int r = mw * 16 + g;
        int cc = nw * 64 + nf * 8 + 2 * t;
        *(__half2*)(sD + r * SD_STRIDE + cc)       = __floats2half2_rn(acc[nf][0], acc[nf][1]);
        *(__half2*)(sD + (r + 8) * SD_STRIDE + cc) = __floats2half2_rn(acc[nf][2], acc[nf][3]);
    }
    __syncthreads();

    // coalesced copy of h rows to global (256B per node)
    #pragma unroll
    for (int j = 0; j < 4; j++) {
        int slot = j * 256 + tid;              // 1024 x 16B
        int row = slot >> 4, off = slot & 15;
        int gn = nodeBase + row;
        if (gn < n) {
            uint4 v = *(const uint4*)((const char*)sD + row * (SD_STRIDE * 2) + off * 16);
            *(uint4*)((char*)g_h + (size_t)gn * 256 + off * 16) = v;
        }
    }

    // att dots: warp w handles nodes w*8 .. w*8+7
    float as00 = att_src[2 * lane],      as01 = att_src[2 * lane + 1];
    float as10 = att_src[64 + 2 * lane], as11 = att_src[64 + 2 * lane + 1];
    float ad00 = att_dst[2 * lane],      ad01 = att_dst[2 * lane + 1];
    float ad10 = att_dst[64 + 2 * lane], ad11 = att_dst[64 + 2 * lane + 1];
    for (int q = 0; q < 8; q++) {
        int r = w * 8 + q;
        int gn = nodeBase + r;
        float2 p0 = __half22float2(*(__half2*)(sD + r * SD_STRIDE + 2 * lane));
        float2 p1 = __half22float2(*(__half2*)(sD + r * SD_STRIDE + 64 + 2 * lane));
        float s0 = p0.x * as00 + p0.y * as01;
        float s1 = p1.x * as10 + p1.y * as11;
        float d0 = p0.x * ad00 + p0.y * ad01;
        float d1 = p1.x * ad10 + p1.y * ad11;
        #pragma unroll
        for (int o = 16; o; o >>= 1) {
            s0 += __shfl_xor_sync(0xffffffffu, s0, o);
            s1 += __shfl_xor_sync(0xffffffffu, s1, o);
            d0 += __shfl_xor_sync(0xffffffffu, d0, o);
            d1 += __shfl_xor_sync(0xffffffffu, d1, o);
        }
        if (lane == 0 && gn < n) {
            *(float2*)&g_asrc[gn * 2] = make_float2(s0, s1);
            *(float2*)&g_adst[gn * 2] = make_float2(d0, d1);
        }
    }
}

// ---------------- K6: per-dst warp — FUSED single-pass softmax aggregation ----------------
// No max-subtraction: logits are O(10) (Glorot-scaled dots), exp() safely in fp32 range.
__global__ __launch_bounds__(256) void k_agg(const float* __restrict__ bias,
                                             float* __restrict__ out, int n) {
    int warp = (blockIdx.x * blockDim.x + threadIdx.x) >> 5;
    int lane = threadIdx.x & 31;
    if (warp >= n) return;
    int node = warp;
    int beg = g_starts[node], end = g_starts[node + 1];

    int head = lane >> 4;
    int c = lane * 4;
    float ad = g_adst[node * 2 + head];

    const __half* __restrict__ hbase = g_h + c;

    float4 A0 = make_float4(0.f,0.f,0.f,0.f), A1 = A0, A2 = A0, A3 = A0;
    float dA = 0.f, dB = 0.f, dC = 0.f, dD = 0.f;

    int i = beg;
    for (; i + 4 <= end; i += 4) {
        int s0 = g_ssrc[i+0], s1 = g_ssrc[i+1], s2 = g_ssrc[i+2], s3 = g_ssrc[i+3];
        float w0 = g_asrc[s0*2+head], w1 = g_asrc[s1*2+head];
        float w2 = g_asrc[s2*2+head], w3 = g_asrc[s3*2+head];
        uint2 r0 = *(const uint2*)&hbase[(size_t)s0*128];
        uint2 r1 = *(const uint2*)&hbase[(size_t)s1*128];
        uint2 r2 = *(const uint2*)&hbase[(size_t)s2*128];
        uint2 r3 = *(const uint2*)&hbase[(size_t)s3*128];
        float a0 = __expf(lrelu_f(w0 + ad));
        float a1 = __expf(lrelu_f(w1 + ad));
        float a2 = __expf(lrelu_f(w2 + ad));
        float a3 = __expf(lrelu_f(w3 + ad));
        dA += a0; dB += a1; dC += a2; dD += a3;
        {
            float2 p = __half22float2(*(__half2*)&r0.x), q = __half22float2(*(__half2*)&r0.y);
            A0.x = fmaf(a0, p.x, A0.x); A0.y = fmaf(a0, p.y, A0.y);
            A0.z = fmaf(a0, q.x, A0.z); A0.w = fmaf(a0, q.y, A0.w);
        }
        {
            float2 p = __half22float2(*(__half2*)&r1.x), q = __half22float2(*(__half2*)&r1.y);
            A1.x = fmaf(a1, p.x, A1.x); A1.y = fmaf(a1, p.y, A1.y);
            A1.z = fmaf(a1, q.x, A1.z); A1.w = fmaf(a1, q.y, A1.w);
        }
        {
            float2 p = __half22float2(*(__half2*)&r2.x), q = __half22float2(*(__half2*)&r2.y);
            A2.x = fmaf(a2, p.x, A2.x); A2.y = fmaf(a2, p.y, A2.y);
            A2.z = fmaf(a2, q.x, A2.z); A2.w = fmaf(a2, q.y, A2.w);
        }
        {
            float2 p = __half22float2(*(__half2*)&r3.x), q = __half22float2(*(__half2*)&r3.y);
            A3.x = fmaf(a3, p.x, A3.x); A3.y = fmaf(a3, p.y, A3.y);
            A3.z = fmaf(a3, q.x, A3.z); A3.w = fmaf(a3, q.y, A3.w);
        }
    }
    for (; i < end; i++) {
        int s = g_ssrc[i];
        float w = g_asrc[s*2+head];
        uint2 r = *(const uint2*)&hbase[(size_t)s*128];
        float a = __expf(lrelu_f(w + ad));
        dA += a;
        float2 p = __half22float2(*(__half2*)&r.x), q = __half22float2(*(__half2*)&r.y);
        A0.x = fmaf(a, p.x, A0.x); A0.y = fmaf(a, p.y, A0.y);
        A0.z = fmaf(a, q.x, A0.z); A0.w = fmaf(a, q.y, A0.w);
    }

    float dsum = (dA + dB) + (dC + dD);
    float inv = 1.f / (dsum + 1e-16f);

    float4 acc;
    acc.x = (A0.x + A1.x) + (A2.x + A3.x);
    acc.y = (A0.y + A1.y) + (A2.y + A3.y);
    acc.z = (A0.z + A1.z) + (A2.z + A3.z);
    acc.w = (A0.w + A1.w) + (A2.w + A3.w);

    float4 bv = *(const float4*)&bias[c];
    *(float4*)&out[(size_t)node * 128 + c] =
        make_float4(fmaf(acc.x, inv, bv.x), fmaf(acc.y, inv, bv.y),
                    fmaf(acc.z, inv, bv.z), fmaf(acc.w, inv, bv.w));
}

// ---------------- launch ----------------
extern "C" void kernel_launch(void* const* d_in, const int* in_sizes, int n_in,
                              void* d_out, int out_size) {
    const float* x       = (const float*)d_in[0];
    const int*   ei      = (const int*)d_in[1];    // int32 (JAX downcasts int64)
    const float* W       = (const float*)d_in[2];
    const float* att_src = (const float*)d_in[3];
    const float* att_dst = (const float*)d_in[4];
    const float* bias    = (const float*)d_in[5];
    float*       out     = (float*)d_out;

    int n = in_sizes[0] / 128;   // 100000
    int e = in_sizes[1] / 2;     // 1600000

    k_init<<<(n + 255) / 256, 256>>>(n);
    k_hist<<<(e + 255) / 256, 256>>>(ei, e);
    k_scan<<<1, 1024>>>(n);
    k_scatter<<<(e + n + 255) / 256, 256>>>(ei, e, n);

    k_gemm<<<(n + 63) / 64, 256>>>(x, W, att_src, att_dst, n);

    k_agg<<<(n + 7) / 8, 256>>>(bias, out, n);
}

// round 11
// speedup vs baseline: 1.0491x; 1.0491x over previous
#include <cuda_runtime.h>
#include <cuda_fp16.h>
#include <math.h>

// Problem constants (fixed by dataset)
#define MAXN 100000
#define MAXE 1600000
#define NEG_SLOPE 0.2f

// ---------------- scratch (static __device__, no allocs) ----------------
__device__ __half g_h[(size_t)MAXN * 128];    // 25.6 MB: h = elu(x)@W, [N,128] fp16
__device__ float g_asrc[MAXN * 2];            // per-node attention halves
__device__ float g_adst[MAXN * 2];
__device__ int   g_deg[MAXN];
__device__ int   g_starts[MAXN + 1];
__device__ int   g_cursor[MAXN];
__device__ int   g_ssrc[MAXE + MAXN];         // src index sorted by dst (incl self loops)

// ---------------- helpers ----------------
__device__ __forceinline__ float elu_f(float v)   { return v > 0.f ? v : expm1f(v); }
__device__ __forceinline__ float lrelu_f(float v) { return v > 0.f ? v : NEG_SLOPE * v; }

__device__ __forceinline__ unsigned long long pack2(float a, float b) {
    unsigned long long r;
    asm("mov.b64 %0, {%1,%2};" : "=l"(r) : "f"(a), "f"(b));
    return r;
}
__device__ __forceinline__ void unpack2(unsigned long long v, float &a, float &b) {
    asm("mov.b64 {%0,%1}, %2;" : "=f"(a), "=f"(b) : "l"(v));
}
// Packed dual-FMA: 2 fp32 FMAs per instruction (PTX-only on Blackwell)
__device__ __forceinline__ void fma2(unsigned long long &c, unsigned long long a, unsigned long long b) {
    asm("fma.rn.f32x2 %0, %1, %2, %0;" : "+l"(c) : "l"(a), "l"(b));
}

// ---------------- K0: init degrees (1 = self loop) + cursors ----------------
__global__ void k_init(int n) {
    int i = blockIdx.x * blockDim.x + threadIdx.x;
    if (i < n) { g_deg[i] = 1; g_cursor[i] = 0; }
}

// ---------------- K1: histogram of dst (edge_index is int32) ----------------
__global__ void k_hist(const int* __restrict__ ei, int e) {
    int i = blockIdx.x * blockDim.x + threadIdx.x;
    if (i < e) {
        int d = __ldcs(ei + e + i);          // streaming read, don't pollute L2
        atomicAdd(&g_deg[d], 1);
    }
}

// ---------------- K2: single-block exclusive scan over deg -> starts ----------------
__global__ void k_scan(int n) {
    __shared__ int part[1024];
    int tid = threadIdx.x;
    int chunk = (n + 1023) >> 10;
    int base = tid * chunk;
    int s = 0;
    for (int i = 0; i < chunk; i++) {
        int id = base + i;
        if (id < n) s += g_deg[id];
    }
    part[tid] = s;
    __syncthreads();
    for (int off = 1; off < 1024; off <<= 1) {
        int v = (tid >= off) ? part[tid - off] : 0;
        __syncthreads();
        part[tid] += v;
        __syncthreads();
    }
    int run = tid ? part[tid - 1] : 0;
    for (int i = 0; i < chunk; i++) {
        int id = base + i;
        if (id < n) { g_starts[id] = run; run += g_deg[id]; }
    }
    if (tid == 1023) g_starts[n] = part[1023];
}

// ---------------- K3: scatter edges into dst-sorted order; self loop at segment end ----------------
__global__ void k_scatter(const int* __restrict__ ei, int e, int n) {
    int i = blockIdx.x * blockDim.x + threadIdx.x;
    if (i < e) {
        int s = __ldcs(ei + i);
        int d = __ldcs(ei + e + i);
        int p = g_starts[d] + atomicAdd(&g_cursor[d], 1);
        g_ssrc[p] = s;
    } else if (i < e + n) {
        int nn = i - e;                     // self loop (nn -> nn)
        g_ssrc[g_starts[nn + 1] - 1] = nn;  // slot deg-1 is reserved for it
    }
}

// ---------------- K4: h = elu(x) @ W  + fused a_src/a_dst epilogue (FFMA2) ----------------
__global__ __launch_bounds__(128) void k_gemm(const float* __restrict__ x,
                                              const float* __restrict__ W,
                                              const float* __restrict__ att_src,
                                              const float* __restrict__ att_dst, int n) {
    __shared__ float sW[64 * 128];   // K-tile 64 x 128 outs (32 KB)
    __shared__ float sX[32 * 68];    // 32 nodes x 64 k (stride 68)
    int tid = threadIdx.x;
    int og = tid & 15, ng = tid >> 4;
    int nodeBase = blockIdx.x * 32;

    unsigned long long acc[4][4];
    #pragma unroll
    for (int a = 0; a < 4; a++)
        #pragma unroll
        for (int j = 0; j < 4; j++) acc[a][j] = 0ull;

    for (int kk = 0; kk < 128; kk += 64) {
        #pragma unroll
        for (int i = 0; i < 16; i++) {
            int idx = i * 128 + tid;
            ((float4*)sW)[idx] = ((const float4*)(W + kk * 128))[idx];
        }
        #pragma unroll
        for (int i = 0; i < 4; i++) {
            int idx = i * 128 + tid;
            int node = idx >> 4;
            int col = idx & 15;
            int gn = nodeBase + node;
            float4 v = make_float4(0.f, 0.f, 0.f, 0.f);
            if (gn < n) v = __ldcs((const float4*)(x + (size_t)gn * 128 + kk) + col);
            v.x = elu_f(v.x); v.y = elu_f(v.y); v.z = elu_f(v.z); v.w = elu_f(v.w);
            ((float4*)(sX + node * 68))[col] = v;
        }
        __syncthreads();

        #pragma unroll 8
        for (int k = 0; k < 64; k++) {
            unsigned long long wv[4];
            #pragma unroll
            for (int j = 0; j < 4; j++)
                wv[j] = *(const unsigned long long*)&sW[k * 128 + og * 2 + j * 32];
            #pragma unroll
            for (int a = 0; a < 4; a++) {
                float xv = sX[(ng * 4 + a) * 68 + k];
                unsigned long long xp = pack2(xv, xv);
                #pragma unroll
                for (int j = 0; j < 4; j++) fma2(acc[a][j], xp, wv[j]);
            }
        }
        __syncthreads();
    }

    float as_v[4][2], ad_v[4][2];
    #pragma unroll
    for (int j = 0; j < 4; j++) {
        int head = j >> 1;
        int ch = og * 2 + (j & 1) * 32;
        as_v[j][0] = att_src[head * 64 + ch];
        as_v[j][1] = att_src[head * 64 + ch + 1];
        ad_v[j][0] = att_dst[head * 64 + ch];
        ad_v[j][1] = att_dst[head * 64 + ch + 1];
    }

    float ps[4][2], pd[4][2];
    #pragma unroll
    for (int a = 0; a < 4; a++) { ps[a][0]=ps[a][1]=pd[a][0]=pd[a][1]=0.f; }

    #pragma unroll
    for (int a = 0; a < 4; a++) {
        int gn = nodeBase + ng * 4 + a;
        #pragma unroll
        for (int j = 0; j < 4; j++) {
            float lo, hi;
            unpack2(acc[a][j], lo, hi);
            int head = j >> 1;
            ps[a][head] += lo * as_v[j][0] + hi * as_v[j][1];
            pd[a][head] += lo * ad_v[j][0] + hi * ad_v[j][1];
            if (gn < n) {
                __half2 hv = __floats2half2_rn(lo, hi);
                *(__half2*)&g_h[(size_t)gn * 128 + og * 2 + j * 32] = hv;
            }
        }
    }

    #pragma unroll
    for (int off = 1; off < 16; off <<= 1) {
        #pragma unroll
        for (int a = 0; a < 4; a++) {
            ps[a][0] += __shfl_xor_sync(0xffffffffu, ps[a][0], off);
            ps[a][1] += __shfl_xor_sync(0xffffffffu, ps[a][1], off);
            pd[a][0] += __shfl_xor_sync(0xffffffffu, pd[a][0], off);
            pd[a][1] += __shfl_xor_sync(0xffffffffu, pd[a][1], off);
        }
    }
    if (og == 0) {
        #pragma unroll
        for (int a = 0; a < 4; a++) {
            int gn = nodeBase + ng * 4 + a;
            if (gn < n) {
                *(float2*)&g_asrc[gn * 2] = make_float2(ps[a][0], ps[a][1]);
                *(float2*)&g_adst[gn * 2] = make_float2(pd[a][0], pd[a][1]);
            }
        }
    }
}

// ---------------- K6: per-dst warp — FUSED single-pass softmax aggregation ----------------
// No max-subtraction: logits are O(10) (Glorot-scaled dots), exp() safely in fp32 range.
// out stores are streaming (__stcs) so they don't evict g_h from L2.
__global__ __launch_bounds__(256) void k_agg(const float* __restrict__ bias,
                                             float* __restrict__ out, int n) {
    int warp = (blockIdx.x * blockDim.x + threadIdx.x) >> 5;
    int lane = threadIdx.x & 31;
    if (warp >= n) return;
    int node = warp;
    int beg = g_starts[node], end = g_starts[node + 1];

    int head = lane >> 4;
    int c = lane * 4;
    float ad = g_adst[node * 2 + head];

    const __half* __restrict__ hbase = g_h + c;

    float4 A0 = make_float4(0.f,0.f,0.f,0.f), A1 = A0, A2 = A0, A3 = A0;
    float dA = 0.f, dB = 0.f, dC = 0.f, dD = 0.f;

    int i = beg;
    for (; i + 4 <= end; i += 4) {
        int s0 = g_ssrc[i+0], s1 = g_ssrc[i+1], s2 = g_ssrc[i+2], s3 = g_ssrc[i+3];
        float w0 = g_asrc[s0*2+head], w1 = g_asrc[s1*2+head];
        float w2 = g_asrc[s2*2+head], w3 = g_asrc[s3*2+head];
        uint2 r0 = *(const uint2*)&hbase[(size_t)s0*128];
        uint2 r1 = *(const uint2*)&hbase[(size_t)s1*128];
        uint2 r2 = *(const uint2*)&hbase[(size_t)s2*128];
        uint2 r3 = *(const uint2*)&hbase[(size_t)s3*128];
        float a0 = __expf(lrelu_f(w0 + ad));
        float a1 = __expf(lrelu_f(w1 + ad));
        float a2 = __expf(lrelu_f(w2 + ad));
        float a3 = __expf(lrelu_f(w3 + ad));
        dA += a0; dB += a1; dC += a2; dD += a3;
        {
            float2 p = __half22float2(*(__half2*)&r0.x), q = __half22float2(*(__half2*)&r0.y);
            A0.x = fmaf(a0, p.x, A0.x); A0.y = fmaf(a0, p.y, A0.y);
            A0.z = fmaf(a0, q.x, A0.z); A0.w = fmaf(a0, q.y, A0.w);
        }
        {
            float2 p = __half22float2(*(__half2*)&r1.x), q = __half22float2(*(__half2*)&r1.y);
            A1.x = fmaf(a1, p.x, A1.x); A1.y = fmaf(a1, p.y, A1.y);
            A1.z = fmaf(a1, q.x, A1.z); A1.w = fmaf(a1, q.y, A1.w);
        }
        {
            float2 p = __half22float2(*(__half2*)&r2.x), q = __half22float2(*(__half2*)&r2.y);
            A2.x = fmaf(a2, p.x, A2.x); A2.y = fmaf(a2, p.y, A2.y);
            A2.z = fmaf(a2, q.x, A2.z); A2.w = fmaf(a2, q.y, A2.w);
        }
        {
            float2 p = __half22float2(*(__half2*)&r3.x), q = __half22float2(*(__half2*)&r3.y);
            A3.x = fmaf(a3, p.x, A3.x); A3.y = fmaf(a3, p.y, A3.y);
            A3.z = fmaf(a3, q.x, A3.z); A3.w = fmaf(a3, q.y, A3.w);
        }
    }
    for (; i < end; i++) {
        int s = g_ssrc[i];
        float w = g_asrc[s*2+head];
        uint2 r = *(const uint2*)&hbase[(size_t)s*128];
        float a = __expf(lrelu_f(w + ad));
        dA += a;
        float2 p = __half22float2(*(__half2*)&r.x), q = __half22float2(*(__half2*)&r.y);
        A0.x = fmaf(a, p.x, A0.x); A0.y = fmaf(a, p.y, A0.y);
        A0.z = fmaf(a, q.x, A0.z); A0.w = fmaf(a, q.y, A0.w);
    }

    float dsum = (dA + dB) + (dC + dD);
    float inv = 1.f / (dsum + 1e-16f);

    float4 acc;
    acc.x = (A0.x + A1.x) + (A2.x + A3.x);
    acc.y = (A0.y + A1.y) + (A2.y + A3.y);
    acc.z = (A0.z + A1.z) + (A2.z + A3.z);
    acc.w = (A0.w + A1.w) + (A2.w + A3.w);

    float4 bv = *(const float4*)&bias[c];
    float4 res = make_float4(fmaf(acc.x, inv, bv.x), fmaf(acc.y, inv, bv.y),
                             fmaf(acc.z, inv, bv.z), fmaf(acc.w, inv, bv.w));
    __stcs((float4*)&out[(size_t)node * 128 + c], res);
}

// ---------------- launch ----------------
extern "C" void kernel_launch(void* const* d_in, const int* in_sizes, int n_in,
                              void* d_out, int out_size) {
    const float* x       = (const float*)d_in[0];
    const int*   ei      = (const int*)d_in[1];    // int32 (JAX downcasts int64)
    const float* W       = (const float*)d_in[2];
    const float* att_src = (const float*)d_in[3];
    const float* att_dst = (const float*)d_in[4];
    const float* bias    = (const float*)d_in[5];
    float*       out     = (float*)d_out;

    int n = in_sizes[0] / 128;   // 100000
    int e = in_sizes[1] / 2;     // 1600000

    // Order: gemm moved between scan and scatter (dep-safe; gemm is independent
    // of the edge pipeline). This also shifts the fixed ncu sampling slot from
    // k_scatter onto k_gemm so the profile finally shows a mainline kernel.
    k_init<<<(n + 255) / 256, 256>>>(n);
    k_hist<<<(e + 255) / 256, 256>>>(ei, e);
    k_scan<<<1, 1024>>>(n);
    k_gemm<<<(n + 31) / 32, 128>>>(x, W, att_src, att_dst, n);
    k_scatter<<<(e + n + 255) / 256, 256>>>(ei, e, n);

    k_agg<<<(n + 7) / 8, 256>>>(bias, out, n);
}

// round 12
// speedup vs baseline: 1.0557x; 1.0064x over previous
#include <cuda_runtime.h>
#include <cuda_fp16.h>
#include <math.h>

// Problem constants (fixed by dataset)
#define MAXN 100000
#define MAXE 1600000
#define NEG_SLOPE 0.2f

// ---------------- scratch (static __device__, no allocs) ----------------
__device__ __half g_h[(size_t)MAXN * 128];    // 25.6 MB: h = elu(x)@W, [N,128] fp16
__device__ float g_asrc[MAXN * 2];            // per-node attention halves
__device__ float g_adst[MAXN * 2];
__device__ int   g_deg[MAXN];
__device__ int   g_starts[MAXN + 1];
__device__ int   g_cursor[MAXN];
__device__ int   g_ssrc[MAXE + MAXN];         // src index sorted by dst (incl self loops)

// ---------------- helpers ----------------
__device__ __forceinline__ float elu_f(float v)   { return v > 0.f ? v : expm1f(v); }
__device__ __forceinline__ float lrelu_f(float v) { return v > 0.f ? v : NEG_SLOPE * v; }

__device__ __forceinline__ unsigned long long pack2(float a, float b) {
    unsigned long long r;
    asm("mov.b64 %0, {%1,%2};" : "=l"(r) : "f"(a), "f"(b));
    return r;
}
__device__ __forceinline__ void unpack2(unsigned long long v, float &a, float &b) {
    asm("mov.b64 {%0,%1}, %2;" : "=f"(a), "=f"(b) : "l"(v));
}
// Packed dual-FMA: 2 fp32 FMAs per instruction (PTX-only on Blackwell)
__device__ __forceinline__ void fma2(unsigned long long &c, unsigned long long a, unsigned long long b) {
    asm("fma.rn.f32x2 %0, %1, %2, %0;" : "+l"(c) : "l"(a), "l"(b));
}

// ---------------- K0: init degrees (1 = self loop) + cursors ----------------
__global__ void k_init(int n) {
    int i = blockIdx.x * blockDim.x + threadIdx.x;
    if (i < n) { g_deg[i] = 1; g_cursor[i] = 0; }
}

// ---------------- K1: histogram of dst (edge_index is int32) ----------------
__global__ void k_hist(const int* __restrict__ ei, int e) {
    int i = blockIdx.x * blockDim.x + threadIdx.x;
    if (i < e) {
        int d = __ldcs(ei + e + i);          // streaming read, don't pollute L2
        atomicAdd(&g_deg[d], 1);
    }
}

// ---------------- K2: single-block exclusive scan over deg -> starts ----------------
__global__ void k_scan(int n) {
    __shared__ int part[1024];
    int tid = threadIdx.x;
    int chunk = (n + 1023) >> 10;
    int base = tid * chunk;
    int s = 0;
    for (int i = 0; i < chunk; i++) {
        int id = base + i;
        if (id < n) s += g_deg[id];
    }
    part[tid] = s;
    __syncthreads();
    for (int off = 1; off < 1024; off <<= 1) {
        int v = (tid >= off) ? part[tid - off] : 0;
        __syncthreads();
        part[tid] += v;
        __syncthreads();
    }
    int run = tid ? part[tid - 1] : 0;
    for (int i = 0; i < chunk; i++) {
        int id = base + i;
        if (id < n) { g_starts[id] = run; run += g_deg[id]; }
    }
    if (tid == 1023) g_starts[n] = part[1023];
}

// ---------------- K3: scatter edges into dst-sorted order; self loop at segment end ----------------
__global__ void k_scatter(const int* __restrict__ ei, int e, int n) {
    int i = blockIdx.x * blockDim.x + threadIdx.x;
    if (i < e) {
        int s = __ldcs(ei + i);
        int d = __ldcs(ei + e + i);
        int p = g_starts[d] + atomicAdd(&g_cursor[d], 1);
        g_ssrc[p] = s;
    } else if (i < e + n) {
        int nn = i - e;                     // self loop (nn -> nn)
        g_ssrc[g_starts[nn + 1] - 1] = nn;  // slot deg-1 is reserved for it
    }
}

// ---------------- K4: h = elu(x) @ W  + fused a_src/a_dst epilogue (FFMA2 v2) ----------------
// K-tile 32; X stored PRE-DUPLICATED as u64 {x,x} so the inner loop has no packs.
// Per 2 k-steps/thread: 4 LDS.128 (xp, broadcast) + 8 LDS.64 (wv, conflict-free)
// + 32 FFMA2  ->  FFMA2 ~73% of issues (was ~53%).
#define KT 32
__global__ __launch_bounds__(128) void k_gemm(const float* __restrict__ x,
                                              const float* __restrict__ W,
                                              const float* __restrict__ att_src,
                                              const float* __restrict__ att_dst, int n) {
    __shared__ float sW[KT * 128];                          // 16 KB
    __shared__ __align__(16) unsigned long long sXd[32 * 34]; // 8.7 KB (stride 34 u64, 16B-aligned pairs)
    int tid = threadIdx.x;
    int og = tid & 15, ng = tid >> 4;
    int nodeBase = blockIdx.x * 32;

    unsigned long long acc[4][4];
    #pragma unroll
    for (int a = 0; a < 4; a++)
        #pragma unroll
        for (int j = 0; j < 4; j++) acc[a][j] = 0ull;

    for (int kk = 0; kk < 128; kk += KT) {
        // W tile: KT x 128 floats = 1024 float4, 8 per thread
        #pragma unroll
        for (int i = 0; i < 8; i++) {
            int idx = i * 128 + tid;
            ((float4*)sW)[idx] = ((const float4*)(W + kk * 128))[idx];
        }
        // X tile: 32 nodes x KT floats = 256 float4, 2 per thread; elu + duplicate
        #pragma unroll
        for (int i = 0; i < 2; i++) {
            int slot = i * 128 + tid;
            int node = slot >> 3;
            int col = slot & 7;
            int gn = nodeBase + node;
            float4 v = make_float4(0.f, 0.f, 0.f, 0.f);
            if (gn < n) v = __ldcs((const float4*)(x + (size_t)gn * 128 + kk) + col);
            v.x = elu_f(v.x); v.y = elu_f(v.y); v.z = elu_f(v.z); v.w = elu_f(v.w);
            unsigned long long* dst = &sXd[node * 34 + col * 4];
            dst[0] = pack2(v.x, v.x);
            dst[1] = pack2(v.y, v.y);
            dst[2] = pack2(v.z, v.z);
            dst[3] = pack2(v.w, v.w);
        }
        __syncthreads();

        #pragma unroll
        for (int k = 0; k < KT; k += 2) {
            unsigned long long wv0[4], wv1[4];
            #pragma unroll
            for (int j = 0; j < 4; j++) {
                wv0[j] = *(const unsigned long long*)&sW[k * 128 + og * 2 + j * 32];
                wv1[j] = *(const unsigned long long*)&sW[(k + 1) * 128 + og * 2 + j * 32];
            }
            #pragma unroll
            for (int a = 0; a < 4; a++) {
                ulonglong2 xp = *(const ulonglong2*)&sXd[(ng * 4 + a) * 34 + k];
                #pragma unroll
                for (int j = 0; j < 4; j++) fma2(acc[a][j], xp.x, wv0[j]);
                #pragma unroll
                for (int j = 0; j < 4; j++) fma2(acc[a][j], xp.y, wv1[j]);
            }
        }
        __syncthreads();
    }

    float as_v[4][2], ad_v[4][2];
    #pragma unroll
    for (int j = 0; j < 4; j++) {
        int head = j >> 1;
        int ch = og * 2 + (j & 1) * 32;
        as_v[j][0] = att_src[head * 64 + ch];
        as_v[j][1] = att_src[head * 64 + ch + 1];
        ad_v[j][0] = att_dst[head * 64 + ch];
        ad_v[j][1] = att_dst[head * 64 + ch + 1];
    }

    float ps[4][2], pd[4][2];
    #pragma unroll
    for (int a = 0; a < 4; a++) { ps[a][0]=ps[a][1]=pd[a][0]=pd[a][1]=0.f; }

    #pragma unroll
    for (int a = 0; a < 4; a++) {
        int gn = nodeBase + ng * 4 + a;
        #pragma unroll
        for (int j = 0; j < 4; j++) {
            float lo, hi;
            unpack2(acc[a][j], lo, hi);
            int head = j >> 1;
            ps[a][head] += lo * as_v[j][0] + hi * as_v[j][1];
            pd[a][head] += lo * ad_v[j][0] + hi * ad_v[j][1];
            if (gn < n) {
                __half2 hv = __floats2half2_rn(lo, hi);
                *(__half2*)&g_h[(size_t)gn * 128 + og * 2 + j * 32] = hv;
            }
        }
    }

    #pragma unroll
    for (int off = 1; off < 16; off <<= 1) {
        #pragma unroll
        for (int a = 0; a < 4; a++) {
            ps[a][0] += __shfl_xor_sync(0xffffffffu, ps[a][0], off);
            ps[a][1] += __shfl_xor_sync(0xffffffffu, ps[a][1], off);
            pd[a][0] += __shfl_xor_sync(0xffffffffu, pd[a][0], off);
            pd[a][1] += __shfl_xor_sync(0xffffffffu, pd[a][1], off);
        }
    }
    if (og == 0) {
        #pragma unroll
        for (int a = 0; a < 4; a++) {
            int gn = nodeBase + ng * 4 + a;
            if (gn < n) {
                *(float2*)&g_asrc[gn * 2] = make_float2(ps[a][0], ps[a][1]);
                *(float2*)&g_adst[gn * 2] = make_float2(pd[a][0], pd[a][1]);
            }
        }
    }
}

// ---------------- K6: per-dst warp — FUSED single-pass softmax aggregation ----------------
// No max-subtraction (logits O(10), safe in fp32). out via __stcs. Unroll x2 to keep
// registers low (unroll x4 measured neutral in R6) -> better occupancy.
__global__ __launch_bounds__(256) void k_agg(const float* __restrict__ bias,
                                             float* __restrict__ out, int n) {
    int warp = (blockIdx.x * blockDim.x + threadIdx.x) >> 5;
    int lane = threadIdx.x & 31;
    if (warp >= n) return;
    int node = warp;
    int beg = g_starts[node], end = g_starts[node + 1];

    int head = lane >> 4;
    int c = lane * 4;
    float ad = g_adst[node * 2 + head];

    const __half* __restrict__ hbase = g_h + c;

    float4 A0 = make_float4(0.f,0.f,0.f,0.f), A1 = A0;
    float dA = 0.f, dB = 0.f;

    int i = beg;
    for (; i + 2 <= end; i += 2) {
        int s0 = g_ssrc[i+0], s1 = g_ssrc[i+1];
        float w0 = g_asrc[s0*2+head], w1 = g_asrc[s1*2+head];
        uint2 r0 = *(const uint2*)&hbase[(size_t)s0*128];
        uint2 r1 = *(const uint2*)&hbase[(size_t)s1*128];
        float a0 = __expf(lrelu_f(w0 + ad));
        float a1 = __expf(lrelu_f(w1 + ad));
        dA += a0; dB += a1;
        {
            float2 p = __half22float2(*(__half2*)&r0.x), q = __half22float2(*(__half2*)&r0.y);
            A0.x = fmaf(a0, p.x, A0.x); A0.y = fmaf(a0, p.y, A0.y);
            A0.z = fmaf(a0, q.x, A0.z); A0.w = fmaf(a0, q.y, A0.w);
        }
        {
            float2 p = __half22float2(*(__half2*)&r1.x), q = __half22float2(*(__half2*)&r1.y);
            A1.x = fmaf(a1, p.x, A1.x); A1.y = fmaf(a1, p.y, A1.y);
            A1.z = fmaf(a1, q.x, A1.z); A1.w = fmaf(a1, q.y, A1.w);
        }
    }
    if (i < end) {
        int s = g_ssrc[i];
        float w = g_asrc[s*2+head];
        uint2 r = *(const uint2*)&hbase[(size_t)s*128];
        float a = __expf(lrelu_f(w + ad));
        dA += a;
        float2 p = __half22float2(*(__half2*)&r.x), q = __half22float2(*(__half2*)&r.y);
        A0.x = fmaf(a, p.x, A0.x); A0.y = fmaf(a, p.y, A0.y);
        A0.z = fmaf(a, q.x, A0.z); A0.w = fmaf(a, q.y, A0.w);
    }

    float inv = 1.f / ((dA + dB) + 1e-16f);

    float4 acc;
    acc.x = A0.x + A1.x;
    acc.y = A0.y + A1.y;
    acc.z = A0.z + A1.z;
    acc.w = A0.w + A1.w;

    float4 bv = *(const float4*)&bias[c];
    float4 res = make_float4(fmaf(acc.x, inv, bv.x), fmaf(acc.y, inv, bv.y),
                             fmaf(acc.z, inv, bv.z), fmaf(acc.w, inv, bv.w));
    __stcs((float4*)&out[(size_t)node * 128 + c], res);
}

// ---------------- launch ----------------
extern "C" void kernel_launch(void* const* d_in, const int* in_sizes, int n_in,
                              void* d_out, int out_size) {
    const float* x       = (const float*)d_in[0];
    const int*   ei      = (const int*)d_in[1];    // int32 (JAX downcasts int64)
    const float* W       = (const float*)d_in[2];
    const float* att_src = (const float*)d_in[3];
    const float* att_dst = (const float*)d_in[4];
    const float* bias    = (const float*)d_in[5];
    float*       out     = (float*)d_out;

    int n = in_sizes[0] / 128;   // 100000
    int e = in_sizes[1] / 2;     // 1600000

    // k_gemm stays in the ncu-sampled 4th slot to verify this round's change.
    k_init<<<(n + 255) / 256, 256>>>(n);
    k_hist<<<(e + 255) / 256, 256>>>(ei, e);
    k_scan<<<1, 1024>>>(n);
    k_gemm<<<(n + 31) / 32, 128>>>(x, W, att_src, att_dst, n);
    k_scatter<<<(e + n + 255) / 256, 256>>>(ei, e, n);

    k_agg<<<(n + 7) / 8, 256>>>(bias, out, n);
}